// round 7
// baseline (speedup 1.0000x reference)
#include <cuda_runtime.h>
#include <cuda_bf16.h>
#include <cstdint>

#define TLEN   128
#define HID    768
#define LHU    256
#define G4     1024
#define S_TOT  256
#define NB     8
#define NGRP   (S_TOT / NB)   // 32
#define BATCH  8
#define NSENT  32

typedef unsigned long long u64;

// ---------------- device scratch ----------------
__device__ float g_WhhX [2][LHU * LHU * 4];              // [dir][k][u][gate]
__device__ float g_G    [2][(size_t)S_TOT * TLEN * G4];  // word pre-gates (268 MB)
__device__ float g_emb  [S_TOT * 2 * LHU];
__device__ float g_WshhX[2][LHU * LHU * 4];
__device__ float g_Gs   [2][S_TOT * G4];
__device__ float g_final[BATCH * 2 * LHU];

// ---------------- helpers ----------------
__device__ __forceinline__ u64 pack2(float lo, float hi) {
    u64 r;
    asm("mov.b64 %0, {%1, %2};" : "=l"(r) : "r"(__float_as_uint(lo)), "r"(__float_as_uint(hi)));
    return r;
}
__device__ __forceinline__ u64 dup2(float x) { return pack2(x, x); }
__device__ __forceinline__ void fma2(u64& a, u64 b, u64 c) {
    asm("fma.rn.f32x2 %0, %1, %2, %0;" : "+l"(a) : "l"(b), "l"(c));
}
__device__ __forceinline__ float2 unpack2(u64 v) {
    unsigned lo, hi;
    asm("mov.b64 {%0, %1}, %2;" : "=r"(lo), "=r"(hi) : "l"(v));
    return make_float2(__uint_as_float(lo), __uint_as_float(hi));
}
__device__ __forceinline__ float sigf(float x) { return 1.f / (1.f + __expf(-x)); }
__device__ __forceinline__ float tanh_(float x) {
    float e = __expf(-2.f * fabsf(x));
    float r = (1.f - e) / (1.f + e);
    return copysignf(r, x);
}
__device__ __forceinline__ uint32_t tf32r(float f) {
    uint32_t o;
    asm("cvt.rna.tf32.f32 %0, %1;" : "=r"(o) : "f"(f));
    return o;
}
#define CLUSTER_ARRIVE() asm volatile("barrier.cluster.arrive.aligned;" ::: "memory")
#define CLUSTER_WAIT()   asm volatile("barrier.cluster.wait.aligned;" ::: "memory")

// ---------------- tiny init (launch-order pad; zeroes g_final legitimately) ----------------
__global__ void init_out() {
    int i = blockIdx.x * 256 + threadIdx.x;
    if (i < BATCH * 2 * LHU) g_final[i] = 0.f;
}

// ---------------- tf32 mma.sync GEMM (R4 config: 128x128 tile, 256 thr, 8 warps 4Mx2N) ----------------
__global__ void __launch_bounds__(256) mma_gemm(
    const float* __restrict__ A,
    const float* __restrict__ B0, const float* __restrict__ B1,
    const float* __restrict__ bias0, const float* __restrict__ bias1,
    float* __restrict__ C0, float* __restrict__ C1,
    int K)
{
    int dir = blockIdx.x >> 3;
    int nt  = blockIdx.x & 7;
    int mt  = blockIdx.y;
    const float* Ap = A + (size_t)mt * 128 * K;
    const float* Bp = (dir ? B1 : B0) + (size_t)nt * 128 * K;
    const float* bi = (dir ? bias1 : bias0) + nt * 128;
    float* Cp = (dir ? C1 : C0) + (size_t)mt * 128 * G4 + nt * 128;

    __shared__ uint32_t As[128][36];
    __shared__ uint32_t Bs[128][36];

    int tid = threadIdx.x;
    int warp = tid >> 5, lane = tid & 31;
    int wm = warp & 3, wn = warp >> 2;
    int lr = lane >> 2, lc = lane & 3;

    float c[2][8][4];
#pragma unroll
    for (int mi = 0; mi < 2; mi++)
#pragma unroll
        for (int ni = 0; ni < 8; ni++)
#pragma unroll
            for (int j = 0; j < 4; j++) c[mi][ni][j] = 0.f;

    int nkt = K >> 5;
    for (int kt = 0; kt < nkt; kt++) {
        __syncthreads();
#pragma unroll
        for (int it = 0; it < 4; it++) {
            int i = tid + it * 256;
            int row = i >> 3, c4 = i & 7;
            float4 va = *(const float4*)(Ap + (size_t)row * K + kt * 32 + c4 * 4);
            float4 vb = *(const float4*)(Bp + (size_t)row * K + kt * 32 + c4 * 4);
            As[row][c4 * 4 + 0] = tf32r(va.x); As[row][c4 * 4 + 1] = tf32r(va.y);
            As[row][c4 * 4 + 2] = tf32r(va.z); As[row][c4 * 4 + 3] = tf32r(va.w);
            Bs[row][c4 * 4 + 0] = tf32r(vb.x); Bs[row][c4 * 4 + 1] = tf32r(vb.y);
            Bs[row][c4 * 4 + 2] = tf32r(vb.z); Bs[row][c4 * 4 + 3] = tf32r(vb.w);
        }
        __syncthreads();

#pragma unroll
        for (int kk = 0; kk < 4; kk++) {
            int k0 = kk * 8;
            uint32_t a[2][4];
#pragma unroll
            for (int mi = 0; mi < 2; mi++) {
                int r = wm * 32 + mi * 16 + lr;
                a[mi][0] = As[r][k0 + lc];
                a[mi][1] = As[r + 8][k0 + lc];
                a[mi][2] = As[r][k0 + lc + 4];
                a[mi][3] = As[r + 8][k0 + lc + 4];
            }
            uint32_t b[8][2];
#pragma unroll
            for (int ni = 0; ni < 8; ni++) {
                int n = wn * 64 + ni * 8 + lr;
                b[ni][0] = Bs[n][k0 + lc];
                b[ni][1] = Bs[n][k0 + lc + 4];
            }
#pragma unroll
            for (int mi = 0; mi < 2; mi++)
#pragma unroll
                for (int ni = 0; ni < 8; ni++) {
                    asm volatile(
                        "mma.sync.aligned.m16n8k8.row.col.f32.tf32.tf32.f32 "
                        "{%0,%1,%2,%3}, {%4,%5,%6,%7}, {%8,%9}, {%0,%1,%2,%3};"
                        : "+f"(c[mi][ni][0]), "+f"(c[mi][ni][1]),
                          "+f"(c[mi][ni][2]), "+f"(c[mi][ni][3])
                        : "r"(a[mi][0]), "r"(a[mi][1]), "r"(a[mi][2]), "r"(a[mi][3]),
                          "r"(b[ni][0]), "r"(b[ni][1]));
                }
        }
    }

#pragma unroll
    for (int mi = 0; mi < 2; mi++) {
        int r0 = wm * 32 + mi * 16 + lr;
#pragma unroll
        for (int ni = 0; ni < 8; ni++) {
            int col = wn * 64 + ni * 8 + 2 * lc;
            float bx = bi[col], by = bi[col + 1];
            *(float2*)(Cp + (size_t)r0 * G4 + col) =
                make_float2(c[mi][ni][0] + bx, c[mi][ni][1] + by);
            *(float2*)(Cp + (size_t)(r0 + 8) * G4 + col) =
                make_float2(c[mi][ni][2] + bx, c[mi][ni][3] + by);
        }
    }
}

// ---------------- weight prep (split into 2 kernels for launch-order control) ----------------
__global__ void prep_word(const float* __restrict__ wlf, const float* __restrict__ wlb) {
    int i = blockIdx.x * blockDim.x + threadIdx.x;
    if (i >= LHU * LHU * 4) return;
    int g = i & 3, u = (i >> 2) & 255, k = i >> 10;
    int src = (g * LHU + u) * LHU + k;
    g_WhhX[0][i] = wlf[src]; g_WhhX[1][i] = wlb[src];
}
__global__ void prep_sent(const float* __restrict__ wsf, const float* __restrict__ wsb) {
    int i = blockIdx.x * blockDim.x + threadIdx.x;
    if (i >= LHU * LHU * 4) return;
    int g = i & 3, u = (i >> 2) & 255, k = i >> 10;
    int src = (g * LHU + u) * LHU + k;
    g_WshhX[0][i] = wsf[src]; g_WshhX[1][i] = wsb[src];
}

// ---------------- word-level BiLSTM + masked mean pool, cluster-2 u-split ----------------
// grid (NGRP*2, 2), cluster (2,1,1). CTA = 8 seqs x 128 u-units (rank picks u-half).
// thread: u = rank*128 + (tid&127), seq-quad = tid>>7. h exchanged via DSMEM per step.
__global__ void __launch_bounds__(256) __cluster_dims__(2, 1, 1)
word_lstm(const int* __restrict__ mask) {
    int tid  = threadIdx.x;
    int grp  = blockIdx.x >> 1;
    int rank = blockIdx.x & 1;
    int dir  = blockIdx.y;
    int s0   = grp * NB;
    int ul   = tid & 127;
    int u    = rank * 128 + ul;
    int half = tid >> 7;            // 0: seqs 0-3, 1: seqs 4-7

    __shared__ __align__(16) float hs[2][LHU][NB];
    __shared__ float ms[NB][TLEN];
    __shared__ float cntS[NB];

    for (int i = tid; i < NB * TLEN; i += 256) {
        int n = i >> 7, t = i & 127;
        ms[n][t] = (float)mask[(s0 + n) * TLEN + t];
    }
    for (int i = tid; i < LHU * NB; i += 256)
        ((float*)hs[0])[i] = 0.f;
    __syncthreads();
    if (tid < NB) {
        float cc = 0.f;
        for (int t = 0; t < TLEN; t++) cc += ms[tid][t];
        cntS[tid] = cc;
    }
    __syncthreads();
    CLUSTER_ARRIVE(); CLUSTER_WAIT();

    float c[4]    = {0.f, 0.f, 0.f, 0.f};
    float pool[4] = {0.f, 0.f, 0.f, 0.f};
    const float*  Gd = g_G[dir];
    const float4* W4 = (const float4*)g_WhhX[dir];
    int buf = 0;

    for (int step = 0; step < TLEN; step++) {
        int t = dir ? (TLEN - 1 - step) : step;
        u64 acc[4][2];
#pragma unroll
        for (int p = 0; p < 2; p++) {
            int n0 = 4 * half + 2 * p;
            const float* g0 = Gd + (size_t)((s0 + n0)     * TLEN + t) * G4 + u;
            const float* g1 = Gd + (size_t)((s0 + n0 + 1) * TLEN + t) * G4 + u;
            acc[0][p] = pack2(g0[0],       g1[0]);
            acc[1][p] = pack2(g0[LHU],     g1[LHU]);
            acc[2][p] = pack2(g0[2 * LHU], g1[2 * LHU]);
            acc[3][p] = pack2(g0[3 * LHU], g1[3 * LHU]);
        }

#pragma unroll 4
        for (int k = 0; k < LHU; k++) {
            float4 w = W4[k * LHU + u];
            ulonglong2 hp = *(const ulonglong2*)&hs[buf][k][4 * half];
            u64 d0 = dup2(w.x), d1 = dup2(w.y), d2 = dup2(w.z), d3 = dup2(w.w);
            fma2(acc[0][0], d0, hp.x); fma2(acc[0][1], d0, hp.y);
            fma2(acc[1][0], d1, hp.x); fma2(acc[1][1], d1, hp.y);
            fma2(acc[2][0], d2, hp.x); fma2(acc[2][1], d2, hp.y);
            fma2(acc[3][0], d3, hp.x); fma2(acc[3][1], d3, hp.y);
        }

        float hn[4];
#pragma unroll
        for (int p = 0; p < 2; p++) {
            float2 vi = unpack2(acc[0][p]);
            float2 vf = unpack2(acc[1][p]);
            float2 vg = unpack2(acc[2][p]);
            float2 vo = unpack2(acc[3][p]);
            int n = 2 * p;
            float cc0 = sigf(vf.x) * c[n] + sigf(vi.x) * tanh_(vg.x);
            c[n] = cc0; hn[n] = sigf(vo.x) * tanh_(cc0);
            pool[n] += ms[4 * half + n][t] * hn[n];
            float cc1 = sigf(vf.y) * c[n + 1] + sigf(vi.y) * tanh_(vg.y);
            c[n + 1] = cc1; hn[n + 1] = sigf(vo.y) * tanh_(cc1);
            pool[n + 1] += ms[4 * half + n + 1][t] * hn[n + 1];
        }

        // local write
        *(float4*)&hs[buf ^ 1][u][4 * half] = make_float4(hn[0], hn[1], hn[2], hn[3]);
        // peer write via DSMEM (same offset in peer CTA's smem)
        {
            uint32_t laddr = (uint32_t)__cvta_generic_to_shared(&hs[buf ^ 1][u][4 * half]);
            uint32_t raddr;
            asm volatile("mapa.shared::cluster.u32 %0, %1, %2;"
                         : "=r"(raddr) : "r"(laddr), "r"(rank ^ 1));
            asm volatile("st.shared::cluster.v4.f32 [%0], {%1,%2,%3,%4};"
                         :: "r"(raddr), "f"(hn[0]), "f"(hn[1]), "f"(hn[2]), "f"(hn[3])
                         : "memory");
        }
        CLUSTER_ARRIVE(); CLUSTER_WAIT();
        buf ^= 1;
    }

#pragma unroll
    for (int j = 0; j < 4; j++) {
        int n = 4 * half + j;
        float cnt = cntS[n];
        g_emb[(s0 + n) * (2 * LHU) + dir * LHU + u] = (cnt > 0.f) ? (pool[j] / cnt) : 0.f;
    }
}

// ---------------- sentence-level LSTM ----------------
__global__ void __launch_bounds__(256) sent_lstm() {
    int b = blockIdx.x, u = threadIdx.x;
    __shared__ float h[LHU];
    h[u] = 0.f;
    float c = 0.f;
    __syncthreads();

    const ulonglong2* W2 = (const ulonglong2*)g_WshhX[0];
    for (int t = 0; t < NSENT; t++) {
        const float* gp = g_Gs[0] + (size_t)(b * NSENT + t) * G4;
        u64 aif = pack2(gp[u],           gp[LHU + u]);
        u64 ago = pack2(gp[2 * LHU + u], gp[3 * LHU + u]);
#pragma unroll 8
        for (int k = 0; k < LHU; k++) {
            ulonglong2 w = W2[k * LHU + u];
            u64 hd = dup2(h[k]);
            fma2(aif, w.x, hd);
            fma2(ago, w.y, hd);
        }
        float2 v1 = unpack2(aif), v2 = unpack2(ago);
        float cc = sigf(v1.y) * c + sigf(v1.x) * tanh_(v2.x);
        c = cc;
        float hn = sigf(v2.y) * tanh_(cc);
        __syncthreads();
        h[u] = hn;
        __syncthreads();
    }
    g_final[b * 2 * LHU + u] = h[u];

    const float* gp = g_Gs[1] + (size_t)(b * NSENT + NSENT - 1) * G4;
    float cc = sigf(gp[u]) * tanh_(gp[2 * LHU + u]);
    g_final[b * 2 * LHU + LHU + u] = sigf(gp[3 * LHU + u]) * tanh_(cc);
}

// ---------------- classifier ----------------
__global__ void classify(const float* __restrict__ cw, const float* __restrict__ cb,
                         float* __restrict__ out) {
    int tid = threadIdx.x;
    if (tid >= 32) return;
    int b = tid >> 2, cc = tid & 3;
    float s = cb[cc];
    for (int k = 0; k < 2 * LHU; k++)
        s += g_final[b * 2 * LHU + k] * cw[cc * 2 * LHU + k];
    out[b * 4 + cc] = s;
}

// ---------------- launch ----------------
extern "C" void kernel_launch(void* const* d_in, const int* in_sizes, int n_in,
                              void* d_out, int out_size) {
    const float* hidden  = (const float*)d_in[0];
    const int*   amask   = (const int*)  d_in[1];
    const float* wl_ih_f = (const float*)d_in[2];
    const float* wl_hh_f = (const float*)d_in[3];
    const float* wl_b_f  = (const float*)d_in[4];
    const float* wl_ih_b = (const float*)d_in[5];
    const float* wl_hh_b = (const float*)d_in[6];
    const float* wl_b_b  = (const float*)d_in[7];
    const float* ws_ih_f = (const float*)d_in[8];
    const float* ws_hh_f = (const float*)d_in[9];
    const float* ws_b_f  = (const float*)d_in[10];
    const float* ws_ih_b = (const float*)d_in[11];
    const float* ws_hh_b = (const float*)d_in[12];
    const float* ws_b_b  = (const float*)d_in[13];
    const float* cls_w   = (const float*)d_in[14];
    const float* cls_b   = (const float*)d_in[15];
    float* out = (float*)d_out;

    float *G0, *Gs0, *emb;
    cudaGetSymbolAddress((void**)&G0,  g_G);
    cudaGetSymbolAddress((void**)&Gs0, g_Gs);
    cudaGetSymbolAddress((void**)&emb, g_emb);
    float* G1  = G0  + (size_t)S_TOT * TLEN * G4;
    float* Gs1 = Gs0 + (size_t)S_TOT * G4;

    // launches #1-#3 (pads so the word GEMM is launch #4 = the profiled one)
    prep_word<<<(LHU * LHU * 4 + 255) / 256, 256>>>(wl_hh_f, wl_hh_b);
    prep_sent<<<(LHU * LHU * 4 + 255) / 256, 256>>>(ws_hh_f, ws_hh_b);
    init_out<<<(BATCH * 2 * LHU + 255) / 256, 256>>>();
    // launch #4: word pre-gates [32768 x 768] @ [1024 x 768]^T per dir  (profiled)
    mma_gemm<<<dim3(16, (S_TOT * TLEN) / 128), 256>>>(
        hidden, wl_ih_f, wl_ih_b, wl_b_f, wl_b_b, G0, G1, HID);
    // launch #5: word BiLSTM, cluster-2 u-split
    word_lstm<<<dim3(NGRP * 2, 2), 256>>>(amask);
    // launch #6: sentence pre-gates
    mma_gemm<<<dim3(16, S_TOT / 128), 256>>>(
        emb, ws_ih_f, ws_ih_b, ws_b_f, ws_b_b, Gs0, Gs1, 2 * LHU);
    sent_lstm<<<BATCH, 256>>>();
    classify<<<1, 32>>>(cls_w, cls_b, out);
}

// round 8
// speedup vs baseline: 1.1682x; 1.1682x over previous
#include <cuda_runtime.h>
#include <cuda_bf16.h>
#include <cstdint>

#define TLEN   128
#define HID    768
#define LHU    256
#define G4     1024
#define S_TOT  256
#define NB     8
#define NGRP   (S_TOT / NB)   // 32
#define BATCH  8
#define NSENT  32

typedef unsigned long long u64;

// ---------------- device scratch ----------------
__device__ float g_WhhX [2][LHU * LHU * 4];              // [dir][k][u][gate]
__device__ float g_G    [2][(size_t)S_TOT * TLEN * G4];  // word pre-gates (268 MB)
__device__ float g_emb  [S_TOT * 2 * LHU];
__device__ float g_WshhX[2][LHU * LHU * 4];
__device__ float g_Gs   [2][S_TOT * G4];
__device__ float g_final[BATCH * 2 * LHU];

// ---------------- helpers ----------------
__device__ __forceinline__ u64 pack2(float lo, float hi) {
    u64 r;
    asm("mov.b64 %0, {%1, %2};" : "=l"(r) : "r"(__float_as_uint(lo)), "r"(__float_as_uint(hi)));
    return r;
}
__device__ __forceinline__ u64 dup2(float x) { return pack2(x, x); }
__device__ __forceinline__ void fma2(u64& a, u64 b, u64 c) {
    asm("fma.rn.f32x2 %0, %1, %2, %0;" : "+l"(a) : "l"(b), "l"(c));
}
__device__ __forceinline__ float2 unpack2(u64 v) {
    unsigned lo, hi;
    asm("mov.b64 {%0, %1}, %2;" : "=r"(lo), "=r"(hi) : "l"(v));
    return make_float2(__uint_as_float(lo), __uint_as_float(hi));
}
__device__ __forceinline__ float sigf(float x) { return 1.f / (1.f + __expf(-x)); }
__device__ __forceinline__ float tanh_(float x) {
    float e = __expf(-2.f * fabsf(x));
    float r = (1.f - e) / (1.f + e);
    return copysignf(r, x);
}
__device__ __forceinline__ uint32_t tf32r(float f) {
    uint32_t o;
    asm("cvt.rna.tf32.f32 %0, %1;" : "=r"(o) : "f"(f));
    return o;
}

// ---------------- tf32 mma.sync GEMM, CTA tile 128x256, 8 warps (2M x 4N), warp tile 64x64 ----------------
// C[dir] = A @ B[dir]^T + bias[dir]. A: [Mt*128, K] row-major. B: [1024, K] row-major.
// grid.x = 8 (nt 0..3 | dir<<2), grid.y = M/128. k-tile 32.
// Dynamic smem: As[128][36] + Bs[256][36] u32 = 55296 B.
#define GEMM_SMEM ((128 * 36 + 256 * 36) * 4)
__global__ void __launch_bounds__(256) mma_gemm(
    const float* __restrict__ A,
    const float* __restrict__ B0, const float* __restrict__ B1,
    const float* __restrict__ bias0, const float* __restrict__ bias1,
    float* __restrict__ C0, float* __restrict__ C1,
    int K)
{
    extern __shared__ uint32_t smq[];
    uint32_t* As = smq;                 // [128][36]
    uint32_t* Bs = smq + 128 * 36;      // [256][36]

    int dir = blockIdx.x >> 2;
    int nt  = blockIdx.x & 3;
    int mt  = blockIdx.y;
    const float* Ap = A + (size_t)mt * 128 * K;
    const float* Bp = (dir ? B1 : B0) + (size_t)nt * 256 * K;
    const float* bi = (dir ? bias1 : bias0) + nt * 256;
    float* Cp = (dir ? C1 : C0) + (size_t)mt * 128 * G4 + nt * 256;

    int tid = threadIdx.x;
    int warp = tid >> 5, lane = tid & 31;
    int wm = warp & 1, wn = warp >> 1;       // warp origin (wm*64, wn*64)
    int lr = lane >> 2, lc = lane & 3;

    float c[4][8][4];
#pragma unroll
    for (int mi = 0; mi < 4; mi++)
#pragma unroll
        for (int ni = 0; ni < 8; ni++)
#pragma unroll
            for (int j = 0; j < 4; j++) c[mi][ni][j] = 0.f;

    int nkt = K >> 5;
    for (int kt = 0; kt < nkt; kt++) {
        __syncthreads();
        // stage A: 128 rows x 32 cols = 1024 float4, 4 per thread
#pragma unroll
        for (int it = 0; it < 4; it++) {
            int i = tid + it * 256;
            int row = i >> 3, c4 = i & 7;
            float4 v = *(const float4*)(Ap + (size_t)row * K + kt * 32 + c4 * 4);
            uint32_t* d = As + row * 36 + c4 * 4;
            d[0] = tf32r(v.x); d[1] = tf32r(v.y); d[2] = tf32r(v.z); d[3] = tf32r(v.w);
        }
        // stage B: 256 rows x 32 cols = 2048 float4, 8 per thread
#pragma unroll
        for (int it = 0; it < 8; it++) {
            int i = tid + it * 256;
            int row = i >> 3, c4 = i & 7;
            float4 v = *(const float4*)(Bp + (size_t)row * K + kt * 32 + c4 * 4);
            uint32_t* d = Bs + row * 36 + c4 * 4;
            d[0] = tf32r(v.x); d[1] = tf32r(v.y); d[2] = tf32r(v.z); d[3] = tf32r(v.w);
        }
        __syncthreads();

#pragma unroll
        for (int kk = 0; kk < 4; kk++) {
            int k0 = kk * 8;
            uint32_t a[4][4];
#pragma unroll
            for (int mi = 0; mi < 4; mi++) {
                int r = wm * 64 + mi * 16 + lr;
                a[mi][0] = As[r * 36 + k0 + lc];
                a[mi][1] = As[(r + 8) * 36 + k0 + lc];
                a[mi][2] = As[r * 36 + k0 + lc + 4];
                a[mi][3] = As[(r + 8) * 36 + k0 + lc + 4];
            }
            uint32_t b[8][2];
#pragma unroll
            for (int ni = 0; ni < 8; ni++) {
                int n = wn * 64 + ni * 8 + lr;
                b[ni][0] = Bs[n * 36 + k0 + lc];
                b[ni][1] = Bs[n * 36 + k0 + lc + 4];
            }
#pragma unroll
            for (int mi = 0; mi < 4; mi++)
#pragma unroll
                for (int ni = 0; ni < 8; ni++) {
                    asm volatile(
                        "mma.sync.aligned.m16n8k8.row.col.f32.tf32.tf32.f32 "
                        "{%0,%1,%2,%3}, {%4,%5,%6,%7}, {%8,%9}, {%0,%1,%2,%3};"
                        : "+f"(c[mi][ni][0]), "+f"(c[mi][ni][1]),
                          "+f"(c[mi][ni][2]), "+f"(c[mi][ni][3])
                        : "r"(a[mi][0]), "r"(a[mi][1]), "r"(a[mi][2]), "r"(a[mi][3]),
                          "r"(b[ni][0]), "r"(b[ni][1]));
                }
        }
    }

    // epilogue
#pragma unroll
    for (int mi = 0; mi < 4; mi++) {
        int r0 = wm * 64 + mi * 16 + lr;
#pragma unroll
        for (int ni = 0; ni < 8; ni++) {
            int col = wn * 64 + ni * 8 + 2 * lc;
            float bx = bi[col], by = bi[col + 1];
            *(float2*)(Cp + (size_t)r0 * G4 + col) =
                make_float2(c[mi][ni][0] + bx, c[mi][ni][1] + by);
            *(float2*)(Cp + (size_t)(r0 + 8) * G4 + col) =
                make_float2(c[mi][ni][2] + bx, c[mi][ni][3] + by);
        }
    }
}

// ---------------- weight prep ----------------
__global__ void prep_word(const float* __restrict__ wlf, const float* __restrict__ wlb) {
    int i = blockIdx.x * blockDim.x + threadIdx.x;
    if (i >= LHU * LHU * 4) return;
    int g = i & 3, u = (i >> 2) & 255, k = i >> 10;
    int src = (g * LHU + u) * LHU + k;
    g_WhhX[0][i] = wlf[src]; g_WhhX[1][i] = wlb[src];
}
__global__ void prep_sent(const float* __restrict__ wsf, const float* __restrict__ wsb) {
    int i = blockIdx.x * blockDim.x + threadIdx.x;
    if (i >= LHU * LHU * 4) return;
    int g = i & 3, u = (i >> 2) & 255, k = i >> 10;
    int src = (g * LHU + u) * LHU + k;
    g_WshhX[0][i] = wsf[src]; g_WshhX[1][i] = wsb[src];
}

// ---------------- word-level BiLSTM + masked mean pool (R4 config restored) ----------------
__global__ void __launch_bounds__(256) word_lstm(const int* __restrict__ mask) {
    int u   = threadIdx.x;
    int grp = blockIdx.x;
    int dir = blockIdx.y;
    int s0  = grp * NB;

    __shared__ __align__(16) float hs[2][LHU][NB];
    __shared__ float ms[NB][TLEN];
    __shared__ float cntS[NB];

    for (int i = u; i < NB * TLEN; i += 256) {
        int n = i >> 7, t = i & 127;
        ms[n][t] = (float)mask[(s0 + n) * TLEN + t];
    }
#pragma unroll
    for (int n = 0; n < NB; n++) hs[0][u][n] = 0.f;
    __syncthreads();
    if (u < NB) {
        float cc = 0.f;
        for (int t = 0; t < TLEN; t++) cc += ms[u][t];
        cntS[u] = cc;
    }

    float c[NB], pool[NB];
#pragma unroll
    for (int n = 0; n < NB; n++) { c[n] = 0.f; pool[n] = 0.f; }

    const float*  Gd = g_G[dir];
    const float4* W4 = (const float4*)g_WhhX[dir];
    int buf = 0;

    for (int step = 0; step < TLEN; step++) {
        int t = dir ? (TLEN - 1 - step) : step;
        u64 acc[4][4];
#pragma unroll
        for (int p = 0; p < 4; p++) {
            const float* g0 = Gd + (size_t)((s0 + 2 * p)     * TLEN + t) * G4 + u;
            const float* g1 = Gd + (size_t)((s0 + 2 * p + 1) * TLEN + t) * G4 + u;
            acc[0][p] = pack2(g0[0],       g1[0]);
            acc[1][p] = pack2(g0[LHU],     g1[LHU]);
            acc[2][p] = pack2(g0[2 * LHU], g1[2 * LHU]);
            acc[3][p] = pack2(g0[3 * LHU], g1[3 * LHU]);
        }

#pragma unroll 4
        for (int k = 0; k < LHU; k++) {
            float4 w = W4[k * LHU + u];
            ulonglong2 h01 = *(const ulonglong2*)&hs[buf][k][0];
            ulonglong2 h23 = *(const ulonglong2*)&hs[buf][k][4];
            u64 hp0 = h01.x, hp1 = h01.y, hp2 = h23.x, hp3 = h23.y;
            u64 d0 = dup2(w.x), d1 = dup2(w.y), d2 = dup2(w.z), d3 = dup2(w.w);
            fma2(acc[0][0], d0, hp0); fma2(acc[0][1], d0, hp1); fma2(acc[0][2], d0, hp2); fma2(acc[0][3], d0, hp3);
            fma2(acc[1][0], d1, hp0); fma2(acc[1][1], d1, hp1); fma2(acc[1][2], d1, hp2); fma2(acc[1][3], d1, hp3);
            fma2(acc[2][0], d2, hp0); fma2(acc[2][1], d2, hp1); fma2(acc[2][2], d2, hp2); fma2(acc[2][3], d2, hp3);
            fma2(acc[3][0], d3, hp0); fma2(acc[3][1], d3, hp1); fma2(acc[3][2], d3, hp2); fma2(acc[3][3], d3, hp3);
        }

        float hn[NB];
#pragma unroll
        for (int p = 0; p < 4; p++) {
            float2 vi = unpack2(acc[0][p]);
            float2 vf = unpack2(acc[1][p]);
            float2 vg = unpack2(acc[2][p]);
            float2 vo = unpack2(acc[3][p]);
            {
                int n = 2 * p;
                float cc = sigf(vf.x) * c[n] + sigf(vi.x) * tanh_(vg.x);
                c[n] = cc; hn[n] = sigf(vo.x) * tanh_(cc);
                pool[n] += ms[n][t] * hn[n];
            }
            {
                int n = 2 * p + 1;
                float cc = sigf(vf.y) * c[n] + sigf(vi.y) * tanh_(vg.y);
                c[n] = cc; hn[n] = sigf(vo.y) * tanh_(cc);
                pool[n] += ms[n][t] * hn[n];
            }
        }
        *(float4*)&hs[buf ^ 1][u][0] = make_float4(hn[0], hn[1], hn[2], hn[3]);
        *(float4*)&hs[buf ^ 1][u][4] = make_float4(hn[4], hn[5], hn[6], hn[7]);
        __syncthreads();
        buf ^= 1;
    }

#pragma unroll
    for (int n = 0; n < NB; n++) {
        float cnt = cntS[n];
        g_emb[(s0 + n) * (2 * LHU) + dir * LHU + u] = (cnt > 0.f) ? (pool[n] / cnt) : 0.f;
    }
}

// ---------------- sentence-level LSTM ----------------
__global__ void __launch_bounds__(256) sent_lstm() {
    int b = blockIdx.x, u = threadIdx.x;
    __shared__ float h[LHU];
    h[u] = 0.f;
    float c = 0.f;
    __syncthreads();

    const ulonglong2* W2 = (const ulonglong2*)g_WshhX[0];
    for (int t = 0; t < NSENT; t++) {
        const float* gp = g_Gs[0] + (size_t)(b * NSENT + t) * G4;
        u64 aif = pack2(gp[u],           gp[LHU + u]);
        u64 ago = pack2(gp[2 * LHU + u], gp[3 * LHU + u]);
#pragma unroll 8
        for (int k = 0; k < LHU; k++) {
            ulonglong2 w = W2[k * LHU + u];
            u64 hd = dup2(h[k]);
            fma2(aif, w.x, hd);
            fma2(ago, w.y, hd);
        }
        float2 v1 = unpack2(aif), v2 = unpack2(ago);
        float cc = sigf(v1.y) * c + sigf(v1.x) * tanh_(v2.x);
        c = cc;
        float hn = sigf(v2.y) * tanh_(cc);
        __syncthreads();
        h[u] = hn;
        __syncthreads();
    }
    g_final[b * 2 * LHU + u] = h[u];

    const float* gp = g_Gs[1] + (size_t)(b * NSENT + NSENT - 1) * G4;
    float cc = sigf(gp[u]) * tanh_(gp[2 * LHU + u]);
    g_final[b * 2 * LHU + LHU + u] = sigf(gp[3 * LHU + u]) * tanh_(cc);
}

// ---------------- classifier ----------------
__global__ void classify(const float* __restrict__ cw, const float* __restrict__ cb,
                         float* __restrict__ out) {
    int tid = threadIdx.x;
    if (tid >= 32) return;
    int b = tid >> 2, cc = tid & 3;
    float s = cb[cc];
    for (int k = 0; k < 2 * LHU; k++)
        s += g_final[b * 2 * LHU + k] * cw[cc * 2 * LHU + k];
    out[b * 4 + cc] = s;
}

// ---------------- launch ----------------
extern "C" void kernel_launch(void* const* d_in, const int* in_sizes, int n_in,
                              void* d_out, int out_size) {
    const float* hidden  = (const float*)d_in[0];
    const int*   amask   = (const int*)  d_in[1];
    const float* wl_ih_f = (const float*)d_in[2];
    const float* wl_hh_f = (const float*)d_in[3];
    const float* wl_b_f  = (const float*)d_in[4];
    const float* wl_ih_b = (const float*)d_in[5];
    const float* wl_hh_b = (const float*)d_in[6];
    const float* wl_b_b  = (const float*)d_in[7];
    const float* ws_ih_f = (const float*)d_in[8];
    const float* ws_hh_f = (const float*)d_in[9];
    const float* ws_b_f  = (const float*)d_in[10];
    const float* ws_ih_b = (const float*)d_in[11];
    const float* ws_hh_b = (const float*)d_in[12];
    const float* ws_b_b  = (const float*)d_in[13];
    const float* cls_w   = (const float*)d_in[14];
    const float* cls_b   = (const float*)d_in[15];
    float* out = (float*)d_out;

    float *G0, *Gs0, *emb;
    cudaGetSymbolAddress((void**)&G0,  g_G);
    cudaGetSymbolAddress((void**)&Gs0, g_Gs);
    cudaGetSymbolAddress((void**)&emb, g_emb);
    float* G1  = G0  + (size_t)S_TOT * TLEN * G4;
    float* Gs1 = Gs0 + (size_t)S_TOT * G4;

    cudaFuncSetAttribute(mma_gemm, cudaFuncAttributeMaxDynamicSharedMemorySize, GEMM_SMEM);

    // launch #1: word pre-gates [32768 x 768] @ [1024 x 768]^T per dir
    mma_gemm<<<dim3(8, (S_TOT * TLEN) / 128), 256, GEMM_SMEM>>>(
        hidden, wl_ih_f, wl_ih_b, wl_b_f, wl_b_b, G0, G1, HID);
    // launches #2, #3: weight prep
    prep_word<<<(LHU * LHU * 4 + 255) / 256, 256>>>(wl_hh_f, wl_hh_b);
    prep_sent<<<(LHU * LHU * 4 + 255) / 256, 256>>>(ws_hh_f, ws_hh_b);
    // launch #4: word BiLSTM (profiled this round)
    word_lstm<<<dim3(NGRP, 2), 256>>>(amask);
    // launch #5: sentence pre-gates
    mma_gemm<<<dim3(8, S_TOT / 128), 256, GEMM_SMEM>>>(
        emb, ws_ih_f, ws_ih_b, ws_b_f, ws_b_b, Gs0, Gs1, 2 * LHU);
    sent_lstm<<<BATCH, 256>>>();
    classify<<<1, 32>>>(cls_w, cls_b, out);
}